// round 1
// baseline (speedup 1.0000x reference)
#include <cuda_runtime.h>

// FIStateProbabilitiesPaulied: B=256 samples, ND=4, NQ=3 -> D=8, L=64 Paulis.
// Per sample:
//   pw = x@kernel + bias                       [64]
//   H  = sum_k pw_k P_k                        8x8 complex Hermitian (built analytically)
//   H = V E V†  (complex Jacobi, fp64)
//   amp = U e0, U = exp(-iH);  P_j = |amp_j|^2
//   dU^{(k)} e0 = V (Phi o (V† P_k V)) V† e0   via F-trick (fp32)
//   g[p][k] = 2 Re(conj(amp_p) damp^{(k)}_p);  h = g*sqrt(1/P)
//   I_b = h^T h  (sum over p)                  [64x64]
//   I_k[j,a,l,b] = x_j x_l I_b[a,b]            [4,64,4,64]
// Output layout: I_k flattened [256*4*64*4*64] then I_b [256*64*64].

#define NSWEEP 8

static __constant__ unsigned char PAIRS[7][4][2] = {
    {{0,7},{1,6},{2,5},{3,4}},
    {{0,1},{2,7},{3,6},{4,5}},
    {{0,2},{3,1},{4,7},{5,6}},
    {{0,3},{4,2},{5,1},{6,7}},
    {{0,4},{5,3},{6,2},{7,1}},
    {{0,5},{6,4},{7,3},{1,2}},
    {{0,6},{7,5},{1,4},{2,3}},
};

__global__ __launch_bounds__(256, 2)
void fi_kernel(const float* __restrict__ x,
               const float* __restrict__ kern,
               const float* __restrict__ bias,
               float* __restrict__ out)
{
    const int i = blockIdx.x;          // sample
    const int tid = threadIdx.x;       // 256 threads

    __shared__ double pw[64];
    __shared__ double Hr[8][8], Hi[8][8];
    __shared__ double Vr[8][8], Vi[8][8];
    __shared__ double ev[8];
    __shared__ double rc[4], rs_[4], r1r[4], r1i[4], r2r[4], r2i[4];
    __shared__ float V32r[8][8], V32i[8][8];
    __shared__ float Phr[8][8], Phi[8][8];
    __shared__ float Fr[8][8], Fi[8][8];
    __shared__ float w32r[8], w32i[8], a32r[8], a32i[8], sIp[8];
    __shared__ float hmat[8][64];
    __shared__ float Ib[64][64];
    __shared__ float xx[16];

    // ---------------- Phase 1: pw = x@kernel + bias, xx = outer(x,x) ----------------
    if (tid < 64) {
        float acc = bias[tid];
        #pragma unroll
        for (int d = 0; d < 4; ++d) acc += x[i*4+d] * kern[d*64+tid];
        pw[tid] = (double)acc;
    }
    if (tid < 16) xx[tid] = x[i*4 + (tid>>2)] * x[i*4 + (tid&3)];
    __syncthreads();

    // ---------------- Phase 2: build H (analytic Paulis), V = I ----------------
    // Pauli k digits (base-4, msb first): d0 acts on row bit2. I=0,X=1,Y=2,Z=3.
    // Entry (r,c) nonzero iff c = r ^ mask(k); phase = i^ph.
    if (tid < 64) {
        int r = tid >> 3, c = tid & 7, m = r ^ c;
        double hr = 0.0, hi = 0.0;
        #pragma unroll
        for (int sel = 0; sel < 8; ++sel) {
            int k = 0, ph = 0;
            #pragma unroll
            for (int q = 0; q < 3; ++q) {
                int bit = 2 - q;
                int mq = (m >> bit) & 1;
                int sq = (sel >> bit) & 1;
                int d = mq ? (sq ? 2 : 1) : (sq ? 3 : 0);
                k = (k << 2) | d;
                int rb = (r >> bit) & 1;
                if (d == 2) ph += rb ? 1 : 3;        // Y: Y01=-i, Y10=+i
                else if (d == 3) ph += rb ? 2 : 0;   // Z: diag(1,-1)
            }
            double wv = pw[k];
            switch (ph & 3) {
                case 0: hr += wv; break;
                case 1: hi += wv; break;
                case 2: hr -= wv; break;
                default: hi -= wv; break;
            }
        }
        Hr[r][c] = hr; Hi[r][c] = hi;
        Vr[r][c] = (r == c) ? 1.0 : 0.0;
        Vi[r][c] = 0.0;
    }
    __syncthreads();

    // ---------------- Phase 3: complex Jacobi eigendecomposition (warp 0, fp64) ----
    // Parallel tournament ordering: 4 disjoint (p,q) rotations per step, 7 steps/sweep.
    // Rotation U: U_pp=c, U_pq=s, U_qp=-s e^{-i phi}, U_qq=c e^{-i phi}, alpha=H[p][q]=m e^{i phi}.
    if (tid < 32) {
        const int pi = tid >> 3;
        const int jj = tid & 7;
        for (int it = 0; it < NSWEEP*7; ++it) {
            const int rd = it % 7;
            if (tid < 4) {
                int p = PAIRS[rd][tid][0], q = PAIRS[rd][tid][1];
                double app = Hr[p][p], aqq = Hr[q][q];
                double ar = Hr[p][q], ai = Hi[p][q];
                double m2 = ar*ar + ai*ai;
                double c, s, er, ei;
                if (m2 < 1e-260) { c = 1.0; s = 0.0; er = 1.0; ei = 0.0; }
                else {
                    double mm = sqrt(m2);
                    er = ar / mm; ei = ai / mm;
                    double tau = (aqq - app) / (2.0 * mm);
                    double tt = ((tau >= 0.0) ? 1.0 : -1.0) /
                                (fabs(tau) + sqrt(1.0 + tau*tau));
                    c = 1.0 / sqrt(1.0 + tt*tt);
                    s = tt * c;
                }
                rc[tid] = c; rs_[tid] = s;
                r1r[tid] = s*er; r1i[tid] = s*ei;   // s e^{i phi}
                r2r[tid] = c*er; r2i[tid] = c*ei;   // c e^{i phi}
            }
            __syncwarp();
            {   // rows: H <- U† H : Hp' = c Hp - (s e^{i phi}) Hq ; Hq' = s Hp + (c e^{i phi}) Hq
                int p = PAIRS[rd][pi][0], q = PAIRS[rd][pi][1];
                double c = rc[pi], s = rs_[pi];
                double w1r = r1r[pi], w1i = r1i[pi], w2r = r2r[pi], w2i = r2i[pi];
                double pr = Hr[p][jj], pim = Hi[p][jj];
                double qr = Hr[q][jj], qi = Hi[q][jj];
                Hr[p][jj] = c*pr  - (w1r*qr - w1i*qi);
                Hi[p][jj] = c*pim - (w1r*qi + w1i*qr);
                Hr[q][jj] = s*pr  + (w2r*qr - w2i*qi);
                Hi[q][jj] = s*pim + (w2r*qi + w2i*qr);
            }
            __syncwarp();
            {   // cols: H <- H U  and  V <- V U  (conjugated factors)
                int p = PAIRS[rd][pi][0], q = PAIRS[rd][pi][1];
                double c = rc[pi], s = rs_[pi];
                double w1r = r1r[pi], w1i = -r1i[pi];
                double w2r = r2r[pi], w2i = -r2i[pi];
                double pr = Hr[jj][p], pim = Hi[jj][p];
                double qr = Hr[jj][q], qi = Hi[jj][q];
                Hr[jj][p] = c*pr  - (w1r*qr - w1i*qi);
                Hi[jj][p] = c*pim - (w1r*qi + w1i*qr);
                Hr[jj][q] = s*pr  + (w2r*qr - w2i*qi);
                Hi[jj][q] = s*pim + (w2r*qi + w2i*qr);
                pr = Vr[jj][p]; pim = Vi[jj][p];
                qr = Vr[jj][q]; qi = Vi[jj][q];
                Vr[jj][p] = c*pr  - (w1r*qr - w1i*qi);
                Vi[jj][p] = c*pim - (w1r*qi + w1i*qr);
                Vr[jj][q] = s*pr  + (w2r*qr - w2i*qi);
                Vi[jj][q] = s*pim + (w2r*qi + w2i*qr);
            }
            __syncwarp();
        }
        if (tid < 8) ev[tid] = Hr[tid][tid];
    }
    __syncthreads();

    // ---------------- Phase 4: fp32 prep: V32, Phi (sinc form), amp, P ----------------
    if (tid < 64) {
        int r = tid >> 3, c = tid & 7;
        V32r[r][c] = (float)Vr[r][c];
        V32i[r][c] = (float)Vi[r][c];
        double dd = 0.5*(ev[r] - ev[c]);
        double mu = 0.5*(ev[r] + ev[c]);
        double sc = (fabs(dd) < 1e-30) ? 1.0 : (sin(dd)/dd);
        double smu, cmu; sincos(mu, &smu, &cmu);
        // Phi_{st} = -i e^{-i mu} sinc(d) = (-sin mu - i cos mu)*sc
        Phr[r][c] = (float)(-smu*sc);
        Phi[r][c] = (float)(-cmu*sc);
    }
    if (tid >= 64 && tid < 72) {
        int j = tid - 64;
        double are = 0.0, aim = 0.0;
        #pragma unroll
        for (int s2 = 0; s2 < 8; ++s2) {
            double se, ce; sincos(ev[s2], &se, &ce);       // e^{-ie} = ce - i se
            double v0r = Vr[0][s2], v0i = Vi[0][s2];
            // t_s = (ce - i se) * conj(V0s)
            double tr  =  ce*v0r - se*v0i;
            double tim = -ce*v0i - se*v0r;
            double vjr = Vr[j][s2], vji = Vi[j][s2];
            are += vjr*tr  - vji*tim;
            aim += vjr*tim + vji*tr;
        }
        double P = are*are + aim*aim;
        a32r[j] = (float)are; a32i[j] = (float)aim;
        sIp[j]  = (float)(1.0/sqrt(P));
        w32r[j] = (float)Vr[0][j];         // w_s = conj(V[0][s])
        w32i[j] = (float)(-Vi[0][j]);
    }
    __syncthreads();

    // ---------------- Phase 5: F[s][r'] = sum_t Phi[s][t] V[r'][t] w[t] ----------------
    if (tid < 64) {
        int s2 = tid >> 3, rp = tid & 7;
        float fr = 0.f, fi = 0.f;
        #pragma unroll
        for (int t = 0; t < 8; ++t) {
            float vr = V32r[rp][t], vi = V32i[rp][t];
            float vwr = vr*w32r[t] - vi*w32i[t];
            float vwi = vr*w32i[t] + vi*w32r[t];
            float pr = Phr[s2][t], pii = Phi[s2][t];
            fr += pr*vwr - pii*vwi;
            fi += pr*vwi + pii*vwr;
        }
        Fr[s2][rp] = fr; Fi[s2][rp] = fi;
    }
    __syncthreads();

    // ---------------- Phase 6: Jacobian -> h[p][k] = g*sqrt(1/P) (one Pauli/thread) ----
    if (tid < 64) {
        int k = tid;
        int d0 = (k>>4)&3, d1 = (k>>2)&3, d2 = k&3;
        int mask = ((d0==1||d0==2)?4:0) | ((d1==1||d1==2)?2:0) | ((d2==1||d2==2)?1:0);
        int phv[8];
        #pragma unroll
        for (int r = 0; r < 8; ++r) {
            int ph = 0;
            int rb2=(r>>2)&1, rb1=(r>>1)&1, rb0=r&1;
            if (d0==2) ph += rb2?1:3; else if (d0==3) ph += rb2?2:0;
            if (d1==2) ph += rb1?1:3; else if (d1==3) ph += rb1?2:0;
            if (d2==2) ph += rb0?1:3; else if (d2==3) ph += rb0?2:0;
            phv[r] = ph & 3;
        }
        float ur[8], ui[8];
        #pragma unroll
        for (int s2 = 0; s2 < 8; ++s2) {
            float aur = 0.f, aui = 0.f;
            #pragma unroll
            for (int r = 0; r < 8; ++r) {
                float cr = V32r[r][s2], ci = -V32i[r][s2];   // conj(V_rs)
                int rp = r ^ mask;
                float fr = Fr[s2][rp], fi = Fi[s2][rp];
                float tr  = cr*fr - ci*fi;
                float tim = cr*fi + ci*fr;
                int ph = phv[r];
                float br, bi;
                if (ph == 0)      { br =  tr;  bi =  tim; }
                else if (ph == 1) { br = -tim; bi =  tr;  }
                else if (ph == 2) { br = -tr;  bi = -tim; }
                else              { br =  tim; bi = -tr;  }
                aur += br; aui += bi;
            }
            ur[s2] = aur; ui[s2] = aui;
        }
        #pragma unroll
        for (int j = 0; j < 8; ++j) {
            float dr = 0.f, di = 0.f;
            #pragma unroll
            for (int s2 = 0; s2 < 8; ++s2) {
                dr += V32r[j][s2]*ur[s2] - V32i[j][s2]*ui[s2];
                di += V32r[j][s2]*ui[s2] + V32i[j][s2]*ur[s2];
            }
            float g = 2.f*(a32r[j]*dr + a32i[j]*di);
            hmat[j][k] = g * sIp[j];
        }
    }
    __syncthreads();

    // ---------------- Phase 7: I_b = h^T h (rank-8 Gram), 16 entries/thread ------------
    {
        int a = tid & 63;
        int bbase = (tid >> 6) << 4;
        float ha[8];
        #pragma unroll
        for (int p = 0; p < 8; ++p) ha[p] = hmat[p][a];
        #pragma unroll
        for (int u = 0; u < 16; ++u) {
            int b = bbase + u;
            float acc = 0.f;
            #pragma unroll
            for (int p = 0; p < 8; ++p) acc += ha[p]*hmat[p][b];
            Ib[a][b] = acc;
        }
    }
    __syncthreads();

    // ---------------- Phase 8: write I_b then I_k = xx[j][l]*Ib[a][b] ------------------
    float* outb = out + (size_t)256*65536 + (size_t)i*4096;
    const float* ibf = &Ib[0][0];
    for (int idx = tid; idx < 4096; idx += 256) outb[idx] = ibf[idx];

    float4* outk = (float4*)out + (size_t)i*16384;
    const float4* ib4 = (const float4*)ibf;
    for (int idx = tid; idx < 16384; idx += 256) {
        int b4 = idx & 15;
        int l  = (idx >> 4) & 3;
        int a  = (idx >> 6) & 63;
        int j  = idx >> 12;
        float sxx = xx[j*4 + l];
        float4 v = ib4[a*16 + b4];
        v.x *= sxx; v.y *= sxx; v.z *= sxx; v.w *= sxx;
        outk[idx] = v;
    }
}

extern "C" void kernel_launch(void* const* d_in, const int* in_sizes, int n_in,
                              void* d_out, int out_size) {
    // Identify inputs by element count (robust to ordering):
    // x: 256*4=1024, kernel: 4*64=256, bias: 64, paulies (unused): anything else.
    const float* x = nullptr; const float* k = nullptr; const float* b = nullptr;
    for (int t = 0; t < n_in; ++t) {
        if (in_sizes[t] == 1024 && !x) x = (const float*)d_in[t];
        else if (in_sizes[t] == 256 && !k) k = (const float*)d_in[t];
        else if (in_sizes[t] == 64 && !b) b = (const float*)d_in[t];
    }
    if (!x) x = (const float*)d_in[0];
    if (!k) k = (const float*)d_in[1];
    if (!b) b = (const float*)d_in[2];
    fi_kernel<<<256, 256>>>(x, k, b, (float*)d_out);
}

// round 2
// speedup vs baseline: 5.3688x; 5.3688x over previous
#include <cuda_runtime.h>

// FIStateProbabilitiesPaulied: B=256 samples, ND=4, NQ=3 -> D=8, L=64 Paulis.
// All-fp32 pipeline (tolerance 1e-3; sinc-form Phi is cancellation-free).
// 2 samples per block (512 threads), grid=128 -> single wave on 148 SMs.
// Output layout: I_k flattened [256*4*64*4*64] then I_b [256*64*64].

#define NSWEEP 6

static __constant__ unsigned char PAIRS[7][4][2] = {
    {{0,7},{1,6},{2,5},{3,4}},
    {{0,1},{2,7},{3,6},{4,5}},
    {{0,2},{3,1},{4,7},{5,6}},
    {{0,3},{4,2},{5,1},{6,7}},
    {{0,4},{5,3},{6,2},{7,1}},
    {{0,5},{6,4},{7,3},{1,2}},
    {{0,6},{7,5},{1,4},{2,3}},
};

__global__ __launch_bounds__(512)
void fi_kernel(const float* __restrict__ x,
               const float* __restrict__ kern,
               const float* __restrict__ bias,
               float* __restrict__ out)
{
    const int half = threadIdx.x >> 8;   // which sample within the block
    const int ltid = threadIdx.x & 255;  // 256 threads per sample
    const int i = (blockIdx.x << 1) + half;

    __shared__ float pw[2][64];
    __shared__ float Hr[2][8][8], Hi[2][8][8];
    __shared__ float Vr[2][8][8], Vi[2][8][8];
    __shared__ float ev[2][8];
    __shared__ float rc[2][4], rs_[2][4], r1r[2][4], r1i[2][4], r2r[2][4], r2i[2][4];
    __shared__ float Phr[2][8][8], Phi[2][8][8];
    __shared__ float Fr[2][8][8], Fi[2][8][8];
    __shared__ float w32r[2][8], w32i[2][8], a32r[2][8], a32i[2][8], sIp[2][8];
    __shared__ float hmat[2][8][64];
    __shared__ float Ib[2][64][64];
    __shared__ float xx[2][16];

    // ---------------- Phase 1: pw = x@kernel + bias, xx = outer(x,x) ----------------
    if (ltid < 64) {
        float acc = bias[ltid];
        #pragma unroll
        for (int d = 0; d < 4; ++d) acc += x[i*4+d] * kern[d*64+ltid];
        pw[half][ltid] = acc;
    }
    if (ltid < 16) xx[half][ltid] = x[i*4 + (ltid>>2)] * x[i*4 + (ltid&3)];
    __syncthreads();

    // ---------------- Phase 2: build H (analytic Paulis), V = I ----------------
    if (ltid < 64) {
        int r = ltid >> 3, c = ltid & 7, m = r ^ c;
        float hr = 0.0f, hi = 0.0f;
        #pragma unroll
        for (int sel = 0; sel < 8; ++sel) {
            int k = 0, ph = 0;
            #pragma unroll
            for (int q = 0; q < 3; ++q) {
                int bit = 2 - q;
                int mq = (m >> bit) & 1;
                int sq = (sel >> bit) & 1;
                int d = mq ? (sq ? 2 : 1) : (sq ? 3 : 0);
                k = (k << 2) | d;
                int rb = (r >> bit) & 1;
                if (d == 2) ph += rb ? 1 : 3;        // Y: Y01=-i, Y10=+i
                else if (d == 3) ph += rb ? 2 : 0;   // Z: diag(1,-1)
            }
            float wv = pw[half][k];
            switch (ph & 3) {
                case 0: hr += wv; break;
                case 1: hi += wv; break;
                case 2: hr -= wv; break;
                default: hi -= wv; break;
            }
        }
        Hr[half][r][c] = hr; Hi[half][r][c] = hi;
        Vr[half][r][c] = (r == c) ? 1.0f : 0.0f;
        Vi[half][r][c] = 0.0f;
    }
    __syncthreads();

    // ---------------- Phase 3: complex Jacobi eigendecomposition (fp32) --------------
    // One warp per sample: sample A -> local warp 0 (global warp 0, SMSP0),
    // sample B -> local warp 1 (global warp 9, SMSP1).
    if ((ltid >> 5) == half) {
        const int lane = ltid & 31;
        const int pi = lane >> 3;
        const int jj = lane & 7;
        for (int it = 0; it < NSWEEP*7; ++it) {
            const int rd = it % 7;
            if (lane < 4) {
                int p = PAIRS[rd][lane][0], q = PAIRS[rd][lane][1];
                float app = Hr[half][p][p], aqq = Hr[half][q][q];
                float ar = Hr[half][p][q], ai = Hi[half][p][q];
                float m2 = ar*ar + ai*ai;
                float c, s, er, ei;
                if (m2 < 1e-24f) { c = 1.0f; s = 0.0f; er = 1.0f; ei = 0.0f; }
                else {
                    float mm = sqrtf(m2);
                    er = ar / mm; ei = ai / mm;
                    float tau = (aqq - app) / (2.0f * mm);
                    float tt = ((tau >= 0.0f) ? 1.0f : -1.0f) /
                                (fabsf(tau) + sqrtf(1.0f + tau*tau));
                    c = 1.0f / sqrtf(1.0f + tt*tt);
                    s = tt * c;
                }
                rc[half][lane] = c; rs_[half][lane] = s;
                r1r[half][lane] = s*er; r1i[half][lane] = s*ei;   // s e^{i phi}
                r2r[half][lane] = c*er; r2i[half][lane] = c*ei;   // c e^{i phi}
            }
            __syncwarp();
            {   // rows: H <- U† H
                int p = PAIRS[rd][pi][0], q = PAIRS[rd][pi][1];
                float c = rc[half][pi], s = rs_[half][pi];
                float w1r = r1r[half][pi], w1i = r1i[half][pi];
                float w2r = r2r[half][pi], w2i = r2i[half][pi];
                float pr = Hr[half][p][jj], pim = Hi[half][p][jj];
                float qr = Hr[half][q][jj], qi = Hi[half][q][jj];
                Hr[half][p][jj] = c*pr  - (w1r*qr - w1i*qi);
                Hi[half][p][jj] = c*pim - (w1r*qi + w1i*qr);
                Hr[half][q][jj] = s*pr  + (w2r*qr - w2i*qi);
                Hi[half][q][jj] = s*pim + (w2r*qi + w2i*qr);
            }
            __syncwarp();
            {   // cols: H <- H U  and  V <- V U  (conjugated factors)
                int p = PAIRS[rd][pi][0], q = PAIRS[rd][pi][1];
                float c = rc[half][pi], s = rs_[half][pi];
                float w1r = r1r[half][pi], w1i = -r1i[half][pi];
                float w2r = r2r[half][pi], w2i = -r2i[half][pi];
                float pr = Hr[half][jj][p], pim = Hi[half][jj][p];
                float qr = Hr[half][jj][q], qi = Hi[half][jj][q];
                Hr[half][jj][p] = c*pr  - (w1r*qr - w1i*qi);
                Hi[half][jj][p] = c*pim - (w1r*qi + w1i*qr);
                Hr[half][jj][q] = s*pr  + (w2r*qr - w2i*qi);
                Hi[half][jj][q] = s*pim + (w2r*qi + w2i*qr);
                pr = Vr[half][jj][p]; pim = Vi[half][jj][p];
                qr = Vr[half][jj][q]; qi = Vi[half][jj][q];
                Vr[half][jj][p] = c*pr  - (w1r*qr - w1i*qi);
                Vi[half][jj][p] = c*pim - (w1r*qi + w1i*qr);
                Vr[half][jj][q] = s*pr  + (w2r*qr - w2i*qi);
                Vi[half][jj][q] = s*pim + (w2r*qi + w2i*qr);
            }
            __syncwarp();
        }
        if (lane < 8) ev[half][lane] = Hr[half][lane][lane];
    }
    __syncthreads();

    // ---------------- Phase 4: Phi (sinc form), amp, P ----------------
    if (ltid < 64) {
        int r = ltid >> 3, c = ltid & 7;
        float dd = 0.5f*(ev[half][r] - ev[half][c]);
        float mu = 0.5f*(ev[half][r] + ev[half][c]);
        float sc = (fabsf(dd) < 1e-8f) ? 1.0f : (sinf(dd)/dd);
        float smu, cmu; sincosf(mu, &smu, &cmu);
        // Phi_{st} = -i e^{-i mu} sinc(d) = (-sin mu - i cos mu)*sc
        Phr[half][r][c] = -smu*sc;
        Phi[half][r][c] = -cmu*sc;
    }
    if (ltid >= 64 && ltid < 72) {
        int j = ltid - 64;
        float are = 0.0f, aim = 0.0f;
        #pragma unroll
        for (int s2 = 0; s2 < 8; ++s2) {
            float se, ce; sincosf(ev[half][s2], &se, &ce);   // e^{-ie} = ce - i se
            float v0r = Vr[half][0][s2], v0i = Vi[half][0][s2];
            float tr  =  ce*v0r - se*v0i;
            float tim = -ce*v0i - se*v0r;
            float vjr = Vr[half][j][s2], vji = Vi[half][j][s2];
            are += vjr*tr  - vji*tim;
            aim += vjr*tim + vji*tr;
        }
        float P = are*are + aim*aim;
        a32r[half][j] = are; a32i[half][j] = aim;
        sIp[half][j]  = rsqrtf(P);
        w32r[half][j] = Vr[half][0][j];          // w_s = conj(V[0][s])
        w32i[half][j] = -Vi[half][0][j];
    }
    __syncthreads();

    // ---------------- Phase 5: F[s][r'] = sum_t Phi[s][t] V[r'][t] w[t] ----------------
    if (ltid < 64) {
        int s2 = ltid >> 3, rp = ltid & 7;
        float fr = 0.f, fi = 0.f;
        #pragma unroll
        for (int t = 0; t < 8; ++t) {
            float vr = Vr[half][rp][t], vi = Vi[half][rp][t];
            float vwr = vr*w32r[half][t] - vi*w32i[half][t];
            float vwi = vr*w32i[half][t] + vi*w32r[half][t];
            float pr = Phr[half][s2][t], pii = Phi[half][s2][t];
            fr += pr*vwr - pii*vwi;
            fi += pr*vwi + pii*vwr;
        }
        Fr[half][s2][rp] = fr; Fi[half][s2][rp] = fi;
    }
    __syncthreads();

    // ---------------- Phase 6: Jacobian -> h[p][k] = g*sqrt(1/P) (one Pauli/thread) ----
    if (ltid < 64) {
        int k = ltid;
        int d0 = (k>>4)&3, d1 = (k>>2)&3, d2 = k&3;
        int mask = ((d0==1||d0==2)?4:0) | ((d1==1||d1==2)?2:0) | ((d2==1||d2==2)?1:0);
        int phv[8];
        #pragma unroll
        for (int r = 0; r < 8; ++r) {
            int ph = 0;
            int rb2=(r>>2)&1, rb1=(r>>1)&1, rb0=r&1;
            if (d0==2) ph += rb2?1:3; else if (d0==3) ph += rb2?2:0;
            if (d1==2) ph += rb1?1:3; else if (d1==3) ph += rb1?2:0;
            if (d2==2) ph += rb0?1:3; else if (d2==3) ph += rb0?2:0;
            phv[r] = ph & 3;
        }
        float ur[8], ui[8];
        #pragma unroll
        for (int s2 = 0; s2 < 8; ++s2) {
            float aur = 0.f, aui = 0.f;
            #pragma unroll
            for (int r = 0; r < 8; ++r) {
                float cr = Vr[half][r][s2], ci = -Vi[half][r][s2];   // conj(V_rs)
                int rp = r ^ mask;
                float fr = Fr[half][s2][rp], fi = Fi[half][s2][rp];
                float tr  = cr*fr - ci*fi;
                float tim = cr*fi + ci*fr;
                int ph = phv[r];
                float br, bi;
                if (ph == 0)      { br =  tr;  bi =  tim; }
                else if (ph == 1) { br = -tim; bi =  tr;  }
                else if (ph == 2) { br = -tr;  bi = -tim; }
                else              { br =  tim; bi = -tr;  }
                aur += br; aui += bi;
            }
            ur[s2] = aur; ui[s2] = aui;
        }
        #pragma unroll
        for (int j = 0; j < 8; ++j) {
            float dr = 0.f, di = 0.f;
            #pragma unroll
            for (int s2 = 0; s2 < 8; ++s2) {
                dr += Vr[half][j][s2]*ur[s2] - Vi[half][j][s2]*ui[s2];
                di += Vr[half][j][s2]*ui[s2] + Vi[half][j][s2]*ur[s2];
            }
            float g = 2.f*(a32r[half][j]*dr + a32i[half][j]*di);
            hmat[half][j][k] = g * sIp[half][j];
        }
    }
    __syncthreads();

    // ---------------- Phase 7: I_b = h^T h (rank-8 Gram), 16 entries/thread ------------
    {
        int a = ltid & 63;
        int bbase = (ltid >> 6) << 4;
        float ha[8];
        #pragma unroll
        for (int p = 0; p < 8; ++p) ha[p] = hmat[half][p][a];
        #pragma unroll
        for (int u = 0; u < 16; ++u) {
            int b = bbase + u;
            float acc = 0.f;
            #pragma unroll
            for (int p = 0; p < 8; ++p) acc += ha[p]*hmat[half][p][b];
            Ib[half][a][b] = acc;
        }
    }
    __syncthreads();

    // ---------------- Phase 8: write I_b then I_k = xx[j][l]*Ib[a][b] ------------------
    float* outb = out + (size_t)256*65536 + (size_t)i*4096;
    const float* ibf = &Ib[half][0][0];
    for (int idx = ltid; idx < 4096; idx += 256) outb[idx] = ibf[idx];

    float4* outk = (float4*)out + (size_t)i*16384;
    const float4* ib4 = (const float4*)ibf;
    for (int idx = ltid; idx < 16384; idx += 256) {
        int b4 = idx & 15;
        int l  = (idx >> 4) & 3;
        int a  = (idx >> 6) & 63;
        int j  = idx >> 12;
        float sxx = xx[half][j*4 + l];
        float4 v = ib4[a*16 + b4];
        v.x *= sxx; v.y *= sxx; v.z *= sxx; v.w *= sxx;
        outk[idx] = v;
    }
}

extern "C" void kernel_launch(void* const* d_in, const int* in_sizes, int n_in,
                              void* d_out, int out_size) {
    const float* x = nullptr; const float* k = nullptr; const float* b = nullptr;
    for (int t = 0; t < n_in; ++t) {
        if (in_sizes[t] == 1024 && !x) x = (const float*)d_in[t];
        else if (in_sizes[t] == 256 && !k) k = (const float*)d_in[t];
        else if (in_sizes[t] == 64 && !b) b = (const float*)d_in[t];
    }
    if (!x) x = (const float*)d_in[0];
    if (!k) k = (const float*)d_in[1];
    if (!b) b = (const float*)d_in[2];
    fi_kernel<<<128, 512>>>(x, k, b, (float*)d_out);
}

// round 4
// speedup vs baseline: 6.4157x; 1.1950x over previous
#include <cuda_runtime.h>

// FIStateProbabilitiesPaulied: B=256, ND=4, NQ=3 -> D=8, L=64.
// Two-kernel split:
//   A: per-sample eigen (fp32 complex Jacobi) + Jacobian -> hmat scratch. Latency-bound, tiny.
//   B: I_b = h^T h, I_k = xx (x) I_b, streams 71MB. Bandwidth-bound, full occupancy.
// Output layout: I_k [256*4*64*4*64] then I_b [256*64*64].

#define NSWEEP 5

__device__ float g_hmat[256 * 512];   // [i][j(8)][k(64)]

static __constant__ unsigned char PAIRS[7][4][2] = {
    {{0,7},{1,6},{2,5},{3,4}},
    {{0,1},{2,7},{3,6},{4,5}},
    {{0,2},{3,1},{4,7},{5,6}},
    {{0,3},{4,2},{5,1},{6,7}},
    {{0,4},{5,3},{6,2},{7,1}},
    {{0,5},{6,4},{7,3},{1,2}},
    {{0,6},{7,5},{1,4},{2,3}},
};

// ======================= Kernel A: eigen + Jacobian =======================
__global__ __launch_bounds__(64)
void eig_kernel(const float* __restrict__ x,
                const float* __restrict__ kern,
                const float* __restrict__ bias)
{
    const int i = blockIdx.x;
    const int tid = threadIdx.x;   // 64 threads

    __shared__ float pw[64];
    __shared__ float Hr[8][8], Hi[8][8];
    __shared__ float Vr[8][8], Vi[8][8];
    __shared__ float ev[8];
    __shared__ float rc[4], rs_[4], r1r[4], r1i[4], r2r[4], r2i[4];
    __shared__ float Phr[8][8], Phi[8][8];
    __shared__ float Fr[8][8], Fi[8][8];
    __shared__ float w32r[8], w32i[8], a32r[8], a32i[8], sIp[8];

    // ---- Phase 1: pw = x@kernel + bias ----
    {
        float acc = bias[tid];
        #pragma unroll
        for (int d = 0; d < 4; ++d) acc += x[i*4+d] * kern[d*64+tid];
        pw[tid] = acc;
    }
    __syncthreads();

    // ---- Phase 2: build H analytically, V = I ----
    {
        int r = tid >> 3, c = tid & 7, m = r ^ c;
        float hr = 0.0f, hi = 0.0f;
        #pragma unroll
        for (int sel = 0; sel < 8; ++sel) {
            int k = 0, ph = 0;
            #pragma unroll
            for (int q = 0; q < 3; ++q) {
                int bit = 2 - q;
                int mq = (m >> bit) & 1;
                int sq = (sel >> bit) & 1;
                int d = mq ? (sq ? 2 : 1) : (sq ? 3 : 0);
                k = (k << 2) | d;
                int rb = (r >> bit) & 1;
                if (d == 2) ph += rb ? 1 : 3;
                else if (d == 3) ph += rb ? 2 : 0;
            }
            float wv = pw[k];
            switch (ph & 3) {
                case 0: hr += wv; break;
                case 1: hi += wv; break;
                case 2: hr -= wv; break;
                default: hi -= wv; break;
            }
        }
        Hr[r][c] = hr; Hi[r][c] = hi;
        Vr[r][c] = (r == c) ? 1.0f : 0.0f;
        Vi[r][c] = 0.0f;
    }
    __syncthreads();

    // ---- Phase 3: complex Jacobi (warp 0, fp32) ----
    if (tid < 32) {
        const int pi = tid >> 3;
        const int jj = tid & 7;
        for (int it = 0; it < NSWEEP*7; ++it) {
            const int rd = it % 7;
            if (tid < 4) {
                int p = PAIRS[rd][tid][0], q = PAIRS[rd][tid][1];
                float app = Hr[p][p], aqq = Hr[q][q];
                float ar = Hr[p][q], ai = Hi[p][q];
                float m2 = ar*ar + ai*ai;
                float c, s, er, ei;
                if (m2 < 1e-24f) { c = 1.0f; s = 0.0f; er = 1.0f; ei = 0.0f; }
                else {
                    float rm = rsqrtf(m2);
                    float mm = m2 * rm;              // sqrt(m2)
                    er = ar * rm; ei = ai * rm;
                    float tau = (aqq - app) / (2.0f * mm);
                    float tt = ((tau >= 0.0f) ? 1.0f : -1.0f) /
                                (fabsf(tau) + sqrtf(1.0f + tau*tau));
                    c = rsqrtf(1.0f + tt*tt);
                    s = tt * c;
                }
                rc[tid] = c; rs_[tid] = s;
                r1r[tid] = s*er; r1i[tid] = s*ei;
                r2r[tid] = c*er; r2i[tid] = c*ei;
            }
            __syncwarp();
            {   // rows: H <- U† H
                int p = PAIRS[rd][pi][0], q = PAIRS[rd][pi][1];
                float c = rc[pi], s = rs_[pi];
                float w1r = r1r[pi], w1i = r1i[pi];
                float w2r = r2r[pi], w2i = r2i[pi];
                float pr = Hr[p][jj], pim = Hi[p][jj];
                float qr = Hr[q][jj], qi = Hi[q][jj];
                Hr[p][jj] = c*pr  - (w1r*qr - w1i*qi);
                Hi[p][jj] = c*pim - (w1r*qi + w1i*qr);
                Hr[q][jj] = s*pr  + (w2r*qr - w2i*qi);
                Hi[q][jj] = s*pim + (w2r*qi + w2i*qr);
            }
            __syncwarp();
            {   // cols: H <- H U, V <- V U
                int p = PAIRS[rd][pi][0], q = PAIRS[rd][pi][1];
                float c = rc[pi], s = rs_[pi];
                float w1r = r1r[pi], w1i = -r1i[pi];
                float w2r = r2r[pi], w2i = -r2i[pi];
                float pr = Hr[jj][p], pim = Hi[jj][p];
                float qr = Hr[jj][q], qi = Hi[jj][q];
                Hr[jj][p] = c*pr  - (w1r*qr - w1i*qi);
                Hi[jj][p] = c*pim - (w1r*qi + w1i*qr);
                Hr[jj][q] = s*pr  + (w2r*qr - w2i*qi);
                Hi[jj][q] = s*pim + (w2r*qi + w2i*qr);
                pr = Vr[jj][p]; pim = Vi[jj][p];
                qr = Vr[jj][q]; qi = Vi[jj][q];
                Vr[jj][p] = c*pr  - (w1r*qr - w1i*qi);
                Vi[jj][p] = c*pim - (w1r*qi + w1i*qr);
                Vr[jj][q] = s*pr  + (w2r*qr - w2i*qi);
                Vi[jj][q] = s*pim + (w2r*qi + w2i*qr);
            }
            __syncwarp();
        }
        if (tid < 8) ev[tid] = Hr[tid][tid];
    }
    __syncthreads();

    // ---- Phase 4: Phi (sinc form) + amp/P/w ----
    {
        int r = tid >> 3, c = tid & 7;
        float dd = 0.5f*(ev[r] - ev[c]);
        float mu = 0.5f*(ev[r] + ev[c]);
        float sc = (fabsf(dd) < 1e-8f) ? 1.0f : (sinf(dd)/dd);
        float smu, cmu; sincosf(mu, &smu, &cmu);
        Phr[r][c] = -smu*sc;
        Phi[r][c] = -cmu*sc;
    }
    if (tid < 8) {
        int j = tid;
        float are = 0.0f, aim = 0.0f;
        #pragma unroll
        for (int s2 = 0; s2 < 8; ++s2) {
            float se, ce; sincosf(ev[s2], &se, &ce);
            float v0r = Vr[0][s2], v0i = Vi[0][s2];
            float tr  =  ce*v0r - se*v0i;
            float tim = -ce*v0i - se*v0r;
            float vjr = Vr[j][s2], vji = Vi[j][s2];
            are += vjr*tr  - vji*tim;
            aim += vjr*tim + vji*tr;
        }
        float P = are*are + aim*aim;
        a32r[j] = are; a32i[j] = aim;
        sIp[j]  = rsqrtf(P);
        w32r[j] = Vr[0][j];
        w32i[j] = -Vi[0][j];
    }
    __syncthreads();

    // ---- Phase 5: F[s][r'] = sum_t Phi[s][t] V[r'][t] w[t] ----
    {
        int s2 = tid >> 3, rp = tid & 7;
        float fr = 0.f, fi = 0.f;
        #pragma unroll
        for (int t = 0; t < 8; ++t) {
            float vr = Vr[rp][t], vi = Vi[rp][t];
            float vwr = vr*w32r[t] - vi*w32i[t];
            float vwi = vr*w32i[t] + vi*w32r[t];
            float pr = Phr[s2][t], pii = Phi[s2][t];
            fr += pr*vwr - pii*vwi;
            fi += pr*vwi + pii*vwr;
        }
        Fr[s2][rp] = fr; Fi[s2][rp] = fi;
    }
    __syncthreads();

    // ---- Phase 6: h[j][k] = g*rsqrt(P), one Pauli per thread -> scratch ----
    {
        int k = tid;
        int d0 = (k>>4)&3, d1 = (k>>2)&3, d2 = k&3;
        int mask = ((d0==1||d0==2)?4:0) | ((d1==1||d1==2)?2:0) | ((d2==1||d2==2)?1:0);
        int phv[8];
        #pragma unroll
        for (int r = 0; r < 8; ++r) {
            int ph = 0;
            int rb2=(r>>2)&1, rb1=(r>>1)&1, rb0=r&1;
            if (d0==2) ph += rb2?1:3; else if (d0==3) ph += rb2?2:0;
            if (d1==2) ph += rb1?1:3; else if (d1==3) ph += rb1?2:0;
            if (d2==2) ph += rb0?1:3; else if (d2==3) ph += rb0?2:0;
            phv[r] = ph & 3;
        }
        float ur[8], ui[8];
        #pragma unroll
        for (int s2 = 0; s2 < 8; ++s2) {
            float aur = 0.f, aui = 0.f;
            #pragma unroll
            for (int r = 0; r < 8; ++r) {
                float cr = Vr[r][s2], ci = -Vi[r][s2];
                int rp = r ^ mask;
                float fr = Fr[s2][rp], fi = Fi[s2][rp];
                float tr  = cr*fr - ci*fi;
                float tim = cr*fi + ci*fr;
                int ph = phv[r];
                float br, bi;
                if (ph == 0)      { br =  tr;  bi =  tim; }
                else if (ph == 1) { br = -tim; bi =  tr;  }
                else if (ph == 2) { br = -tr;  bi = -tim; }
                else              { br =  tim; bi = -tr;  }
                aur += br; aui += bi;
            }
            ur[s2] = aur; ui[s2] = aui;
        }
        float* hout = g_hmat + (size_t)i*512;
        #pragma unroll
        for (int j = 0; j < 8; ++j) {
            float dr = 0.f, di = 0.f;
            #pragma unroll
            for (int s2 = 0; s2 < 8; ++s2) {
                dr += Vr[j][s2]*ur[s2] - Vi[j][s2]*ui[s2];
                di += Vr[j][s2]*ui[s2] + Vi[j][s2]*ur[s2];
            }
            float g = 2.f*(a32r[j]*dr + a32i[j]*di);
            hout[j*64 + k] = g * sIp[j];
        }
    }
}

// ======================= Kernel B: Gram + streaming store =======================
__global__ __launch_bounds__(256)
void out_kernel(const float* __restrict__ x,
                float* __restrict__ out)
{
    const int i = blockIdx.x;
    const int tid = threadIdx.x;

    __shared__ float hmat[8][64];
    __shared__ float Ib[64][64];
    __shared__ float xx[16];

    // load hmat (512 floats)
    {
        const float4* hsrc = (const float4*)(g_hmat + (size_t)i*512);
        float4* hdst = (float4*)&hmat[0][0];
        if (tid < 128) hdst[tid] = hsrc[tid];
    }
    if (tid < 16) xx[tid] = x[i*4 + (tid>>2)] * x[i*4 + (tid&3)];
    __syncthreads();

    // Ib = h^T h  (rank-8), 16 entries/thread
    {
        int a = tid & 63;
        int bbase = (tid >> 6) << 4;
        float ha[8];
        #pragma unroll
        for (int p = 0; p < 8; ++p) ha[p] = hmat[p][a];
        #pragma unroll
        for (int u = 0; u < 16; ++u) {
            int b = bbase + u;
            float acc = 0.f;
            #pragma unroll
            for (int p = 0; p < 8; ++p) acc += ha[p]*hmat[p][b];
            Ib[a][b] = acc;
        }
    }
    __syncthreads();

    // write I_b
    {
        float4* outb = (float4*)(out + (size_t)256*65536 + (size_t)i*4096);
        const float4* ib4 = (const float4*)&Ib[0][0];
        #pragma unroll
        for (int u = 0; u < 4; ++u) outb[tid + 256*u] = ib4[tid + 256*u];
    }

    // write I_k[j][a][l][b] = xx[j*4+l] * Ib[a][b]
    {
        float4* outk = (float4*)out + (size_t)i*16384;
        const float4* ib4 = (const float4*)&Ib[0][0];
        #pragma unroll
        for (int u = 0; u < 64; ++u) {
            int idx = tid + 256*u;
            int b4 = idx & 15;
            int l  = (idx >> 4) & 3;
            int a  = (idx >> 6) & 63;
            int j  = idx >> 12;
            float sxx = xx[j*4 + l];
            float4 v = ib4[a*16 + b4];
            v.x *= sxx; v.y *= sxx; v.z *= sxx; v.w *= sxx;
            outk[idx] = v;
        }
    }
}

extern "C" void kernel_launch(void* const* d_in, const int* in_sizes, int n_in,
                              void* d_out, int out_size) {
    const float* x = nullptr; const float* k = nullptr; const float* b = nullptr;
    for (int t = 0; t < n_in; ++t) {
        if (in_sizes[t] == 1024 && !x) x = (const float*)d_in[t];
        else if (in_sizes[t] == 256 && !k) k = (const float*)d_in[t];
        else if (in_sizes[t] == 64 && !b) b = (const float*)d_in[t];
    }
    if (!x) x = (const float*)d_in[0];
    if (!k) k = (const float*)d_in[1];
    if (!b) b = (const float*)d_in[2];
    eig_kernel<<<256, 64>>>(x, k, b);
    out_kernel<<<256, 256>>>(x, (float*)d_out);
}